// round 16
// baseline (speedup 1.0000x reference)
#include <cuda_runtime.h>
#include <cuda_fp16.h>
#include <math.h>

#define B_    4096
#define INF   64
#define KM    16
#define SQ    32
#define HH    64
#define NMD   48
#define NH    512
#define NTG   512         // G table points (intermediate, smem-only)
#define NTH   1024        // H table points
#define PMAXF 8.0f

#define ROWS  32
#define XSTR  56          // xs fp16 row stride (112B rows)
#define ASTR  520         // a1 fp16 row stride (1040B, ldmatrix conflict-free)
#define NST   8           // cp.async B pipeline depth

// Scratch (no allocations allowed)
__device__ float h_tab[KM * NTH];                        // H_k(x) = mean_s G_k(x t_s)
__device__ __align__(16) __half w2f_frag[NH * NH];       // uint4 slot = kf*1024 + w*32 + lane
__device__ __align__(16) __half w1f_frag[3 * 16 * NH];   // layer-1 B frags, kf<3

// ---------------------------------------------------------------------------
// helpers
// ---------------------------------------------------------------------------
__device__ __forceinline__ unsigned long long pack2(float lo, float hi) {
    unsigned long long r;
    asm("mov.b64 %0, {%1, %2};" : "=l"(r) : "f"(lo), "f"(hi));
    return r;
}
__device__ __forceinline__ float2 unpack2(unsigned long long v) {
    float2 r;
    asm("mov.b64 {%0, %1}, %2;" : "=f"(r.x), "=f"(r.y) : "l"(v));
    return r;
}
__device__ __forceinline__ void fma2(unsigned long long& d,
                                     unsigned long long a,
                                     unsigned long long b) {
    asm("fma.rn.f32x2 %0, %1, %2, %0;" : "+l"(d) : "l"(a), "l"(b));
}
__device__ __forceinline__ unsigned smem_u32(const void* p) {
    unsigned r;
    asm("{ .reg .u64 t; cvta.to.shared.u64 t, %1; cvt.u32.u64 %0, t; }"
        : "=r"(r) : "l"(p));
    return r;
}
__device__ __forceinline__ void ldsm_x4(unsigned& r0, unsigned& r1,
                                        unsigned& r2, unsigned& r3, unsigned addr) {
    asm volatile("ldmatrix.sync.aligned.m8n8.x4.shared.b16 {%0,%1,%2,%3}, [%4];"
                 : "=r"(r0), "=r"(r1), "=r"(r2), "=r"(r3) : "r"(addr));
}
__device__ __forceinline__ void mma_f16(float* c, const unsigned* a, const unsigned* b) {
    asm volatile(
        "mma.sync.aligned.m16n8k16.row.col.f32.f16.f16.f32 "
        "{%0,%1,%2,%3}, {%4,%5,%6,%7}, {%8,%9}, {%0,%1,%2,%3};"
        : "+f"(c[0]), "+f"(c[1]), "+f"(c[2]), "+f"(c[3])
        : "r"(a[0]), "r"(a[1]), "r"(a[2]), "r"(a[3]), "r"(b[0]), "r"(b[1]));
}
__device__ __forceinline__ void cp16(unsigned saddr, const void* gptr) {
    asm volatile("cp.async.cg.shared.global [%0], [%1], 16;"
                 :: "r"(saddr), "l"(gptr) : "memory");
}
__device__ __forceinline__ void cp_commit() {
    asm volatile("cp.async.commit_group;" ::: "memory");
}
template <int N>
__device__ __forceinline__ void cp_wait() {
    asm volatile("cp.async.wait_group %0;" :: "n"(N) : "memory");
}

// ---------------------------------------------------------------------------
// Kernel 0: MERGED setup, one launch, 296 blocks x 256 threads.
// Blocks 0-15: per-k table. G(512 pts) in smem, then H(1024 pts) -> h_tab.
// Blocks 16-295: w2 + w1 -> fp16 MMA B-frag order (2 threads per uint4 slot).
// ---------------------------------------------------------------------------
__global__ void __launch_bounds__(256) setup_kernel(
    const float* __restrict__ w2,  const float* __restrict__ w1,
    const float* __restrict__ mw1, const float* __restrict__ mb1,
    const float* __restrict__ mw2, const float* __restrict__ mb2,
    const float* __restrict__ mw3, const float* __restrict__ mb3)
{
    __shared__ float s_w2[HH * HH];
    __shared__ float s_w1[HH], s_b1[HH], s_b2[HH], s_w3[HH];
    __shared__ float s_g[NTG];

    const int tid = threadIdx.x;

    if (blockIdx.x >= 16) {
        // ---- prep path ----
        int t = (blockIdx.x - 16) * 256 + tid;
        if (t < 65536) {
            int nf   = t & 1;
            int slot = t >> 1;
            int lane = slot & 31;
            int w    = (slot >> 5) & 31;
            int kf   = slot >> 10;
            int kb   = kf * 16 + (lane & 3) * 2;
            int j    = w * 16 + nf * 8 + (lane >> 2);
            __half2 q0 = __floats2half2_rn(__ldg(w2 + (kb + 0) * NH + j),
                                           __ldg(w2 + (kb + 1) * NH + j));
            __half2 q1 = __floats2half2_rn(__ldg(w2 + (kb + 8) * NH + j),
                                           __ldg(w2 + (kb + 9) * NH + j));
            uint2 st;
            st.x = *(unsigned*)&q0;
            st.y = *(unsigned*)&q1;
            ((uint2*)w2f_frag)[slot * 2 + nf] = st;
        } else if (t < 65536 + 6144) {
            int t2   = t - 65536;
            int nf   = t2 & 1;
            int slot = t2 >> 1;
            int lane = slot & 31;
            int w    = (slot >> 5) & 31;
            int kf   = slot >> 10;                // 0..2
            int kb   = kf * 16 + (lane & 3) * 2;
            int j    = w * 16 + nf * 8 + (lane >> 2);
            __half2 q0 = __floats2half2_rn(__ldg(w1 + (kb + 0) * NH + j),
                                           __ldg(w1 + (kb + 1) * NH + j));
            __half2 q1 = __floats2half2_rn(__ldg(w1 + (kb + 8) * NH + j),
                                           __ldg(w1 + (kb + 9) * NH + j));
            uint2 st;
            st.x = *(unsigned*)&q0;
            st.y = *(unsigned*)&q1;
            ((uint2*)w1f_frag)[slot * 2 + nf] = st;
        }
        return;
    }

    // ---- table path: this block owns k = blockIdx.x ----
    const int k = blockIdx.x;
    {
        const float4* src = (const float4*)(mw2 + k * HH * HH);
        float4* dst = (float4*)s_w2;
        for (int idx = tid; idx < HH * HH / 4; idx += 256)
            dst[idx] = src[idx];
    }
    if (tid < HH) {
        s_w1[tid] = mw1[k * HH + tid];
        s_b1[tid] = mb1[k * HH + tid];
        s_b2[tid] = mb2[k * HH + tid];
        s_w3[tid] = mw3[k * HH + tid];
    }
    __syncthreads();

    const float mb3k = __ldg(mb3 + k);
    const int jh = tid & 1;
#pragma unroll 1
    for (int e = 0; e < 2; e++) {
        int i = e * 128 + (tid >> 1);     // 2 passes x 128 entries x 2 thr
        float p = -PMAXF + (2.f * PMAXF / (NTG - 1)) * (float)i;

        float h1v[HH];
#pragma unroll
        for (int h = 0; h < HH; h++)
            h1v[h] = tanhf(fmaf(p, s_w1[h], s_b1[h]));

        float z = 0.f;
#pragma unroll 2
        for (int jg = 0; jg < 8; jg++) {
            int j0 = jh * 32 + jg * 4;
            unsigned long long accA = pack2(s_b2[j0],     s_b2[j0 + 1]);
            unsigned long long accB = pack2(s_b2[j0 + 2], s_b2[j0 + 3]);
#pragma unroll
            for (int h = 0; h < HH; h++) {
                ulonglong2 w = *(const ulonglong2*)&s_w2[h * HH + j0];
                unsigned long long ad = pack2(h1v[h], h1v[h]);
                fma2(accA, w.x, ad);
                fma2(accB, w.y, ad);
            }
            float2 va = unpack2(accA);
            float2 vb = unpack2(accB);
            z = fmaf(s_w3[j0 + 0], tanhf(va.x), z);
            z = fmaf(s_w3[j0 + 1], tanhf(va.y), z);
            z = fmaf(s_w3[j0 + 2], tanhf(vb.x), z);
            z = fmaf(s_w3[j0 + 3], tanhf(vb.y), z);
        }
        z += __shfl_down_sync(0xffffffffu, z, 1, 2);
        if (jh == 0) {
            z += mb3k;
            s_g[i] = fmaxf(z, 0.f) + log1pf(expf(-fabsf(z)));
        }
    }
    // cover entries 256..511 (second half): e-loop above only covered 0..255
#pragma unroll 1
    for (int e = 0; e < 2; e++) {
        int i = 256 + e * 128 + (tid >> 1);
        float p = -PMAXF + (2.f * PMAXF / (NTG - 1)) * (float)i;

        float h1v[HH];
#pragma unroll
        for (int h = 0; h < HH; h++)
            h1v[h] = tanhf(fmaf(p, s_w1[h], s_b1[h]));

        float z = 0.f;
#pragma unroll 2
        for (int jg = 0; jg < 8; jg++) {
            int j0 = jh * 32 + jg * 4;
            unsigned long long accA = pack2(s_b2[j0],     s_b2[j0 + 1]);
            unsigned long long accB = pack2(s_b2[j0 + 2], s_b2[j0 + 3]);
#pragma unroll
            for (int h = 0; h < HH; h++) {
                ulonglong2 w = *(const ulonglong2*)&s_w2[h * HH + j0];
                unsigned long long ad = pack2(h1v[h], h1v[h]);
                fma2(accA, w.x, ad);
                fma2(accB, w.y, ad);
            }
            float2 va = unpack2(accA);
            float2 vb = unpack2(accB);
            z = fmaf(s_w3[j0 + 0], tanhf(va.x), z);
            z = fmaf(s_w3[j0 + 1], tanhf(va.y), z);
            z = fmaf(s_w3[j0 + 2], tanhf(vb.x), z);
            z = fmaf(s_w3[j0 + 3], tanhf(vb.y), z);
        }
        z += __shfl_down_sync(0xffffffffu, z, 1, 2);
        if (jh == 0) {
            z += mb3k;
            s_g[i] = fmaxf(z, 0.f) + log1pf(expf(-fabsf(z)));
        }
    }
    __syncthreads();

    // ---- H: 1024 entries, 4 per thread, 32 lerps each from smem G ----
    const float gscale = (float)(NTG - 1) / (2.f * PMAXF);
#pragma unroll 1
    for (int e = 0; e < 4; e++) {
        int i = e * 256 + tid;
        float x = -PMAXF + (2.f * PMAXF / (NTH - 1)) * (float)i;
        float acc = 0.f;
#pragma unroll
        for (int s = 0; s < SQ; s++) {
            float t = (float)s * (1.f / (SQ - 1));
            float f = (x * t + PMAXF) * gscale;
            f = fminf(fmaxf(f, 0.f), (float)(NTG - 1) - 1e-3f);
            int i0 = (int)f;
            float fr = f - (float)i0;
            float g0 = s_g[i0];
            float g1 = s_g[i0 + 1];
            acc += fmaf(fr, g1 - g0, g0);
        }
        h_tab[k * NTH + i] = acc * (1.f / SQ);
    }
}

// ---------------------------------------------------------------------------
// Kernel 1: fused layer1-MMA + mono(H-lerp) + layer2 fp16-MMA.
// 512 threads (16 warps), grid 128. Warp owns cols [warp*32, warp*32+32)
// in BOTH layers (2 B slots). A-ldsm traffic halved vs 32-warp layout.
// ---------------------------------------------------------------------------
__global__ void __launch_bounds__(512) fused_kernel(
    const float* __restrict__ X,  const float* __restrict__ wlin,
    const float* __restrict__ b1, const float* __restrict__ b2,
    const float* __restrict__ w3, const float* __restrict__ b3,
    float* __restrict__ out)
{
    extern __shared__ float sm[];
    uint4*  bstage = (uint4*)sm;                          // [NST][1024] uint4 = 128KB
    __half* a1f    = (__half*)(bstage + NST * 1024);      // [32][ASTR]
    __half* xs_h   = a1f + ROWS * ASTR;                   // [32][XSTR]
    float*  wpart  = (float*)(xs_h + ROWS * XSTR);        // [16][32]
    float*  mono_s = wpart + 16 * 32;                     // [32]

    const int tid  = threadIdx.x;
    const int warp = tid >> 5;
    const int lane = tid & 31;
    const int b0   = blockIdx.x * ROWS;

    // ---- prime B pipeline: warp copies slots 2w, 2w+1 ----
    const uint4* bgm0 = (const uint4*)w2f_frag + (2 * warp) * 32 + lane;
    const uint4* bgm1 = bgm0 + 32;
    const unsigned bst0 = smem_u32(bstage) + ((2 * warp) * 32 + lane) * 16;
    const unsigned bst1 = bst0 + 512;
#pragma unroll
    for (int s = 0; s < NST - 1; s++) {
        cp16(bst0 + s * 16384, bgm0 + s * 1024);
        cp16(bst1 + s * 16384, bgm1 + s * 1024);
        cp_commit();
    }

    const int arow  = lane & 15;
    const int acol8 = (lane >> 4) * 8;

    // ---- stage x_nm as fp16 row-major [r][i] ----
    for (int idx = tid; idx < ROWS * NMD; idx += 512) {
        int r = idx / NMD, i = idx % NMD;
        xs_h[r * XSTR + i] = __float2half_rn(X[(b0 + r) * INF + KM + i]);
    }
    __syncthreads();

    // ---- layer 1: MMA, warp owns cols [warp*32, warp*32+32) (2 slots) ----
    {
        float acc[2][2][2][4];   // [slot][m][nf][e]
#pragma unroll
        for (int s = 0; s < 2; s++)
#pragma unroll
            for (int m = 0; m < 2; m++)
#pragma unroll
                for (int nf = 0; nf < 2; nf++)
#pragma unroll
                    for (int e = 0; e < 4; e++) acc[s][m][nf][e] = 0.f;

        const unsigned xs_u = smem_u32(xs_h);
#pragma unroll
        for (int kf = 0; kf < 3; kf++) {
            uint4 bw0 = ((const uint4*)w1f_frag)[kf * 1024 + (2 * warp) * 32 + lane];
            uint4 bw1 = ((const uint4*)w1f_frag)[kf * 1024 + (2 * warp + 1) * 32 + lane];
            unsigned bfr[2][2][2] = {{{bw0.x, bw0.y}, {bw0.z, bw0.w}},
                                     {{bw1.x, bw1.y}, {bw1.z, bw1.w}}};
            unsigned a[2][4];
#pragma unroll
            for (int m = 0; m < 2; m++) {
                unsigned off = ((m * 16 + arow) * XSTR + kf * 16 + acol8) * 2;
                ldsm_x4(a[m][0], a[m][1], a[m][2], a[m][3], xs_u + off);
            }
#pragma unroll
            for (int s = 0; s < 2; s++)
#pragma unroll
                for (int m = 0; m < 2; m++)
#pragma unroll
                    for (int nf = 0; nf < 2; nf++)
                        mma_f16(acc[s][m][nf], a[m], bfr[s][nf]);
        }
        // epilogue: bias + relu -> a1f
#pragma unroll
        for (int s = 0; s < 2; s++)
#pragma unroll
            for (int m = 0; m < 2; m++)
#pragma unroll
                for (int nf = 0; nf < 2; nf++) {
                    int j  = (2 * warp + s) * 16 + nf * 8 + (lane & 3) * 2;
                    int r0 = m * 16 + (lane >> 2);
                    float2 bv = *(const float2*)(b1 + j);
                    __half2 lo = __floats2half2_rn(fmaxf(acc[s][m][nf][0] + bv.x, 0.f),
                                                   fmaxf(acc[s][m][nf][1] + bv.y, 0.f));
                    __half2 hi = __floats2half2_rn(fmaxf(acc[s][m][nf][2] + bv.x, 0.f),
                                                   fmaxf(acc[s][m][nf][3] + bv.y, 0.f));
                    *(__half2*)(a1f + r0 * ASTR + j)       = lo;
                    *(__half2*)(a1f + (r0 + 8) * ASTR + j) = hi;
                }
    }

    // ---- mono term: single H-table lerp per (row, k), all 512 threads ----
    {
        int r  = tid >> 4;
        int kk = tid & 15;
        const float scale = (float)(NTH - 1) / (2.f * PMAXF);
        float x = __ldg(X + (b0 + r) * INF + kk);
        const float* tk = h_tab + kk * NTH;
        float f = (x + PMAXF) * scale;
        f = fminf(fmaxf(f, 0.f), (float)(NTH - 1) - 1e-3f);
        int i0 = (int)f;
        float fr = f - (float)i0;
        float h0 = tk[i0];
        float h1 = tk[i0 + 1];
        float part = fmaf(fr, h1 - h0, h0) * x * __ldg(wlin + kk);
#pragma unroll
        for (int off = 8; off; off >>= 1)
            part += __shfl_down_sync(0xffffffffu, part, off, 16);
        if ((tid & 15) == 0) mono_s[r] = part;
    }
    __syncthreads();

    // ---- layer 2: fp16 MMA, warp owns 32 cols; B ring, A dbl-buffered ----
    {
        float acc[2][4][4];      // [m][nf 0..3][e]
#pragma unroll
        for (int m = 0; m < 2; m++)
#pragma unroll
            for (int nf = 0; nf < 4; nf++)
#pragma unroll
                for (int e = 0; e < 4; e++) acc[m][nf][e] = 0.f;

        const unsigned a1_u = smem_u32(a1f);
        const uint4* bsm0 = bstage + (2 * warp) * 32 + lane;
        const uint4* bsm1 = bsm0 + 32;

        unsigned a[2][2][4];
#pragma unroll
        for (int m = 0; m < 2; m++) {
            unsigned off = ((m * 16 + arow) * ASTR + acol8) * 2;
            ldsm_x4(a[0][m][0], a[0][m][1], a[0][m][2], a[0][m][3], a1_u + off);
        }
        cp_wait<NST - 2>();                 // stage 0 ready
        uint4 bq0 = bsm0[0];
        uint4 bq1 = bsm1[0];

        for (int kf = 0; kf < 32; kf++) {
            int cur = kf & 1, nxt = cur ^ 1;
            int sl = kf + NST - 1;
            if (sl < 32) {
                cp16(bst0 + (sl & (NST - 1)) * 16384, bgm0 + sl * 1024);
                cp16(bst1 + (sl & (NST - 1)) * 16384, bgm1 + sl * 1024);
            }
            cp_commit();
            if (kf + 1 < 32) {
#pragma unroll
                for (int m = 0; m < 2; m++) {
                    unsigned off = ((m * 16 + arow) * ASTR + (kf + 1) * 16 + acol8) * 2;
                    ldsm_x4(a[nxt][m][0], a[nxt][m][1], a[nxt][m][2], a[nxt][m][3],
                            a1_u + off);
                }
            }
            unsigned bfr[4][2] = {{bq0.x, bq0.y}, {bq0.z, bq0.w},
                                  {bq1.x, bq1.y}, {bq1.z, bq1.w}};
            cp_wait<NST - 2>();
            if (kf + 1 < 32) {
                bq0 = bsm0[((kf + 1) & (NST - 1)) * 1024];
                bq1 = bsm1[((kf + 1) & (NST - 1)) * 1024];
            }
#pragma unroll
            for (int m = 0; m < 2; m++)
#pragma unroll
                for (int nf = 0; nf < 4; nf++)
                    mma_f16(acc[m][nf], a[cur][m], bfr[nf]);
        }

        // epilogue: relu(acc + b2) . w3 -> per-row partials (32-col slice)
#pragma unroll
        for (int m = 0; m < 2; m++) {
            float p0 = 0.f, p1 = 0.f;
#pragma unroll
            for (int nf = 0; nf < 4; nf++) {
                int col = warp * 32 + nf * 8 + (lane & 3) * 2;
                float2 b2v = *(const float2*)(b2 + col);
                float2 w3v = *(const float2*)(w3 + col);
                p0 = fmaf(fmaxf(acc[m][nf][0] + b2v.x, 0.f), w3v.x, p0);
                p0 = fmaf(fmaxf(acc[m][nf][1] + b2v.y, 0.f), w3v.y, p0);
                p1 = fmaf(fmaxf(acc[m][nf][2] + b2v.x, 0.f), w3v.x, p1);
                p1 = fmaf(fmaxf(acc[m][nf][3] + b2v.y, 0.f), w3v.y, p1);
            }
            p0 += __shfl_xor_sync(0xffffffffu, p0, 1);
            p0 += __shfl_xor_sync(0xffffffffu, p0, 2);
            p1 += __shfl_xor_sync(0xffffffffu, p1, 1);
            p1 += __shfl_xor_sync(0xffffffffu, p1, 2);
            if ((lane & 3) == 0) {
                int r0 = m * 16 + (lane >> 2);
                wpart[warp * 32 + r0]     = p0;
                wpart[warp * 32 + r0 + 8] = p1;
            }
        }
    }
    __syncthreads();

    // ---- final: sum 16 warp slices + bias + mono ----
    if (tid < ROWS) {
        float s = 0.f;
#pragma unroll
        for (int w = 0; w < 16; w++) s += wpart[w * 32 + tid];
        out[b0 + tid] = s + __ldg(b3) + mono_s[tid];
    }
}

// ---------------------------------------------------------------------------
extern "C" void kernel_launch(void* const* d_in, const int* in_sizes, int n_in,
                              void* d_out, int out_size)
{
    const float* x    = (const float*)d_in[0];
    const float* mw1  = (const float*)d_in[1];
    const float* mb1  = (const float*)d_in[2];
    const float* mw2  = (const float*)d_in[3];
    const float* mb2  = (const float*)d_in[4];
    const float* mw3  = (const float*)d_in[5];
    const float* mb3  = (const float*)d_in[6];
    const float* wlin = (const float*)d_in[7];
    const float* nw1  = (const float*)d_in[8];
    const float* nb1  = (const float*)d_in[9];
    const float* nw2  = (const float*)d_in[10];
    const float* nb2  = (const float*)d_in[11];
    const float* nw3  = (const float*)d_in[12];
    const float* nb3  = (const float*)d_in[13];
    float* out = (float*)d_out;

    int smem = NST * 1024 * 16
             + (ROWS * ASTR + ROWS * XSTR) * (int)sizeof(__half)
             + (16 * 32 + 32) * (int)sizeof(float);   // ~166 KB
    cudaFuncSetAttribute(fused_kernel, cudaFuncAttributeMaxDynamicSharedMemorySize, smem);

    setup_kernel<<<296, 256>>>(nw2, nw1, mw1, mb1, mw2, mb2, mw3, mb3);
    fused_kernel<<<B_ / ROWS, 512, smem>>>(x, wlin, nb1, nb2, nw3, nb3, out);
}

// round 17
// speedup vs baseline: 1.8439x; 1.8439x over previous
#include <cuda_runtime.h>
#include <cuda_fp16.h>
#include <math.h>

#define B_    4096
#define INF   64
#define KM    16
#define SQ    32
#define HH    64
#define NMD   48
#define NH    512
#define NTG   512         // G table points
#define NTH   1024        // H table points
#define PMAXF 8.0f

#define ROWS  32
#define XSTR  56          // xs fp16 row stride (112B rows)
#define ASTR  520         // a1 fp16 row stride (1040B, ldmatrix conflict-free)
#define NST   8           // cp.async B pipeline depth

// Scratch (no allocations allowed)
__device__ float g_tab[KM * NTG];                        // intermediate G_k(p)
__device__ float h_tab[KM * NTH];                        // H_k(x) = mean_s G_k(x t_s)
__device__ __align__(16) __half w2f_frag[NH * NH];       // uint4 slot = kf*1024 + w*32 + lane
__device__ __align__(16) __half w1f_frag[3 * 16 * NH];   // layer-1 B frags, kf<3

// ---------------------------------------------------------------------------
// helpers
// ---------------------------------------------------------------------------
__device__ __forceinline__ unsigned long long pack2(float lo, float hi) {
    unsigned long long r;
    asm("mov.b64 %0, {%1, %2};" : "=l"(r) : "f"(lo), "f"(hi));
    return r;
}
__device__ __forceinline__ float2 unpack2(unsigned long long v) {
    float2 r;
    asm("mov.b64 {%0, %1}, %2;" : "=f"(r.x), "=f"(r.y) : "l"(v));
    return r;
}
__device__ __forceinline__ void fma2(unsigned long long& d,
                                     unsigned long long a,
                                     unsigned long long b) {
    asm("fma.rn.f32x2 %0, %1, %2, %0;" : "+l"(d) : "l"(a), "l"(b));
}
__device__ __forceinline__ unsigned smem_u32(const void* p) {
    unsigned r;
    asm("{ .reg .u64 t; cvta.to.shared.u64 t, %1; cvt.u32.u64 %0, t; }"
        : "=r"(r) : "l"(p));
    return r;
}
__device__ __forceinline__ void ldsm_x4(unsigned& r0, unsigned& r1,
                                        unsigned& r2, unsigned& r3, unsigned addr) {
    asm volatile("ldmatrix.sync.aligned.m8n8.x4.shared.b16 {%0,%1,%2,%3}, [%4];"
                 : "=r"(r0), "=r"(r1), "=r"(r2), "=r"(r3) : "r"(addr));
}
__device__ __forceinline__ void mma_f16(float* c, const unsigned* a, const unsigned* b) {
    asm volatile(
        "mma.sync.aligned.m16n8k16.row.col.f32.f16.f16.f32 "
        "{%0,%1,%2,%3}, {%4,%5,%6,%7}, {%8,%9}, {%0,%1,%2,%3};"
        : "+f"(c[0]), "+f"(c[1]), "+f"(c[2]), "+f"(c[3])
        : "r"(a[0]), "r"(a[1]), "r"(a[2]), "r"(a[3]), "r"(b[0]), "r"(b[1]));
}
__device__ __forceinline__ void cp16(unsigned saddr, const void* gptr) {
    asm volatile("cp.async.cg.shared.global [%0], [%1], 16;"
                 :: "r"(saddr), "l"(gptr) : "memory");
}
__device__ __forceinline__ void cp_commit() {
    asm volatile("cp.async.commit_group;" ::: "memory");
}
template <int N>
__device__ __forceinline__ void cp_wait() {
    asm volatile("cp.async.wait_group %0;" :: "n"(N) : "memory");
}

// ---------------------------------------------------------------------------
// Kernel 0: merged setup wave. Blocks 0-63: G-table (4 blocks/k, 2 thr/entry).
// Blocks 64-343: w2 + w1 -> fp16 MMA B-frag order (2 threads per uint4 slot).
// ---------------------------------------------------------------------------
__global__ void __launch_bounds__(256) setup1_kernel(
    const float* __restrict__ w2,  const float* __restrict__ w1,
    const float* __restrict__ mw1, const float* __restrict__ mb1,
    const float* __restrict__ mw2, const float* __restrict__ mb2,
    const float* __restrict__ mw3, const float* __restrict__ mb3)
{
    __shared__ float s_w2[HH * HH];
    __shared__ float s_w1[HH], s_b1[HH], s_b2[HH], s_w3[HH];

    const int tid = threadIdx.x;

    if (blockIdx.x >= 64) {
        // ---- prep path ----
        int t = (blockIdx.x - 64) * 256 + tid;
        if (t < 65536) {
            int nf   = t & 1;
            int slot = t >> 1;
            int lane = slot & 31;
            int w    = (slot >> 5) & 31;
            int kf   = slot >> 10;
            int kb   = kf * 16 + (lane & 3) * 2;
            int j    = w * 16 + nf * 8 + (lane >> 2);
            __half2 q0 = __floats2half2_rn(__ldg(w2 + (kb + 0) * NH + j),
                                           __ldg(w2 + (kb + 1) * NH + j));
            __half2 q1 = __floats2half2_rn(__ldg(w2 + (kb + 8) * NH + j),
                                           __ldg(w2 + (kb + 9) * NH + j));
            uint2 st;
            st.x = *(unsigned*)&q0;
            st.y = *(unsigned*)&q1;
            ((uint2*)w2f_frag)[slot * 2 + nf] = st;
        } else if (t < 65536 + 6144) {
            int t2   = t - 65536;
            int nf   = t2 & 1;
            int slot = t2 >> 1;
            int lane = slot & 31;
            int w    = (slot >> 5) & 31;
            int kf   = slot >> 10;                // 0..2
            int kb   = kf * 16 + (lane & 3) * 2;
            int j    = w * 16 + nf * 8 + (lane >> 2);
            __half2 q0 = __floats2half2_rn(__ldg(w1 + (kb + 0) * NH + j),
                                           __ldg(w1 + (kb + 1) * NH + j));
            __half2 q1 = __floats2half2_rn(__ldg(w1 + (kb + 8) * NH + j),
                                           __ldg(w1 + (kb + 9) * NH + j));
            uint2 st;
            st.x = *(unsigned*)&q0;
            st.y = *(unsigned*)&q1;
            ((uint2*)w1f_frag)[slot * 2 + nf] = st;
        }
        return;
    }

    // ---- G-table path: 4 blocks per k, 128 entries each, 2 thr/entry ----
    int k  = blockIdx.x >> 2;
    int i  = (blockIdx.x & 3) * 128 + (tid >> 1);
    int jh = tid & 1;

    {
        const float4* src = (const float4*)(mw2 + k * HH * HH);
        float4* dst = (float4*)s_w2;
        for (int idx = tid; idx < HH * HH / 4; idx += 256)
            dst[idx] = src[idx];
    }
    if (tid < HH) {
        s_w1[tid] = mw1[k * HH + tid];
        s_b1[tid] = mb1[k * HH + tid];
        s_b2[tid] = mb2[k * HH + tid];
        s_w3[tid] = mw3[k * HH + tid];
    }
    __syncthreads();

    float p = -PMAXF + (2.f * PMAXF / (NTG - 1)) * (float)i;

    float h1v[HH];
#pragma unroll
    for (int h = 0; h < HH; h++)
        h1v[h] = tanhf(fmaf(p, s_w1[h], s_b1[h]));

    float z = 0.f;
#pragma unroll 2
    for (int jg = 0; jg < 8; jg++) {
        int j0 = jh * 32 + jg * 4;
        unsigned long long accA = pack2(s_b2[j0],     s_b2[j0 + 1]);
        unsigned long long accB = pack2(s_b2[j0 + 2], s_b2[j0 + 3]);
#pragma unroll
        for (int h = 0; h < HH; h++) {
            ulonglong2 w = *(const ulonglong2*)&s_w2[h * HH + j0];
            unsigned long long ad = pack2(h1v[h], h1v[h]);
            fma2(accA, w.x, ad);
            fma2(accB, w.y, ad);
        }
        float2 va = unpack2(accA);
        float2 vb = unpack2(accB);
        z = fmaf(s_w3[j0 + 0], tanhf(va.x), z);
        z = fmaf(s_w3[j0 + 1], tanhf(va.y), z);
        z = fmaf(s_w3[j0 + 2], tanhf(vb.x), z);
        z = fmaf(s_w3[j0 + 3], tanhf(vb.y), z);
    }
    z += __shfl_down_sync(0xffffffffu, z, 1, 2);
    if (jh == 0) {
        z += __ldg(mb3 + k);
        g_tab[k * NTG + i] = fmaxf(z, 0.f) + log1pf(expf(-fabsf(z)));
    }
}

// ---------------------------------------------------------------------------
// Kernel 0b: H_k(x) = (1/32) sum_s G_k(x t_s). 128 blocks x 128 threads.
// ---------------------------------------------------------------------------
__global__ void __launch_bounds__(128) hk_kernel()
{
    int idx = blockIdx.x * 128 + threadIdx.x;   // 16384 entries
    int k = idx >> 10;
    int i = idx & (NTH - 1);
    float x = -PMAXF + (2.f * PMAXF / (NTH - 1)) * (float)i;
    const float* tk = g_tab + k * NTG;
    const float scale = (float)(NTG - 1) / (2.f * PMAXF);

    float acc = 0.f;
#pragma unroll
    for (int s = 0; s < SQ; s++) {
        float t = (float)s * (1.f / (SQ - 1));
        float f = (x * t + PMAXF) * scale;
        f = fminf(fmaxf(f, 0.f), (float)(NTG - 1) - 1e-3f);
        int i0 = (int)f;
        float fr = f - (float)i0;
        float g0 = tk[i0];
        float g1 = tk[i0 + 1];
        acc += fmaf(fr, g1 - g0, g0);
    }
    h_tab[idx] = acc * (1.f / SQ);
}

// ---------------------------------------------------------------------------
// Kernel 1: fused layer1-MMA + mono(H-lerp) + layer2 fp16-MMA.  (R16, proven)
// 512 threads (16 warps), grid 128. Warp owns cols [warp*32, warp*32+32).
// ---------------------------------------------------------------------------
__global__ void __launch_bounds__(512) fused_kernel(
    const float* __restrict__ X,  const float* __restrict__ wlin,
    const float* __restrict__ b1, const float* __restrict__ b2,
    const float* __restrict__ w3, const float* __restrict__ b3,
    float* __restrict__ out)
{
    extern __shared__ float sm[];
    uint4*  bstage = (uint4*)sm;                          // [NST][1024] uint4 = 128KB
    __half* a1f    = (__half*)(bstage + NST * 1024);      // [32][ASTR]
    __half* xs_h   = a1f + ROWS * ASTR;                   // [32][XSTR]
    float*  wpart  = (float*)(xs_h + ROWS * XSTR);        // [16][32]
    float*  mono_s = wpart + 16 * 32;                     // [32]

    const int tid  = threadIdx.x;
    const int warp = tid >> 5;
    const int lane = tid & 31;
    const int b0   = blockIdx.x * ROWS;

    // ---- prime B pipeline: warp copies slots 2w, 2w+1 ----
    const uint4* bgm0 = (const uint4*)w2f_frag + (2 * warp) * 32 + lane;
    const uint4* bgm1 = bgm0 + 32;
    const unsigned bst0 = smem_u32(bstage) + ((2 * warp) * 32 + lane) * 16;
    const unsigned bst1 = bst0 + 512;
#pragma unroll
    for (int s = 0; s < NST - 1; s++) {
        cp16(bst0 + s * 16384, bgm0 + s * 1024);
        cp16(bst1 + s * 16384, bgm1 + s * 1024);
        cp_commit();
    }

    const int arow  = lane & 15;
    const int acol8 = (lane >> 4) * 8;

    // ---- stage x_nm as fp16 row-major [r][i] ----
    for (int idx = tid; idx < ROWS * NMD; idx += 512) {
        int r = idx / NMD, i = idx % NMD;
        xs_h[r * XSTR + i] = __float2half_rn(X[(b0 + r) * INF + KM + i]);
    }
    __syncthreads();

    // ---- layer 1: MMA, warp owns cols [warp*32, warp*32+32) (2 slots) ----
    {
        float acc[2][2][2][4];   // [slot][m][nf][e]
#pragma unroll
        for (int s = 0; s < 2; s++)
#pragma unroll
            for (int m = 0; m < 2; m++)
#pragma unroll
                for (int nf = 0; nf < 2; nf++)
#pragma unroll
                    for (int e = 0; e < 4; e++) acc[s][m][nf][e] = 0.f;

        const unsigned xs_u = smem_u32(xs_h);
#pragma unroll
        for (int kf = 0; kf < 3; kf++) {
            uint4 bw0 = ((const uint4*)w1f_frag)[kf * 1024 + (2 * warp) * 32 + lane];
            uint4 bw1 = ((const uint4*)w1f_frag)[kf * 1024 + (2 * warp + 1) * 32 + lane];
            unsigned bfr[2][2][2] = {{{bw0.x, bw0.y}, {bw0.z, bw0.w}},
                                     {{bw1.x, bw1.y}, {bw1.z, bw1.w}}};
            unsigned a[2][4];
#pragma unroll
            for (int m = 0; m < 2; m++) {
                unsigned off = ((m * 16 + arow) * XSTR + kf * 16 + acol8) * 2;
                ldsm_x4(a[m][0], a[m][1], a[m][2], a[m][3], xs_u + off);
            }
#pragma unroll
            for (int s = 0; s < 2; s++)
#pragma unroll
                for (int m = 0; m < 2; m++)
#pragma unroll
                    for (int nf = 0; nf < 2; nf++)
                        mma_f16(acc[s][m][nf], a[m], bfr[s][nf]);
        }
        // epilogue: bias + relu -> a1f
#pragma unroll
        for (int s = 0; s < 2; s++)
#pragma unroll
            for (int m = 0; m < 2; m++)
#pragma unroll
                for (int nf = 0; nf < 2; nf++) {
                    int j  = (2 * warp + s) * 16 + nf * 8 + (lane & 3) * 2;
                    int r0 = m * 16 + (lane >> 2);
                    float2 bv = *(const float2*)(b1 + j);
                    __half2 lo = __floats2half2_rn(fmaxf(acc[s][m][nf][0] + bv.x, 0.f),
                                                   fmaxf(acc[s][m][nf][1] + bv.y, 0.f));
                    __half2 hi = __floats2half2_rn(fmaxf(acc[s][m][nf][2] + bv.x, 0.f),
                                                   fmaxf(acc[s][m][nf][3] + bv.y, 0.f));
                    *(__half2*)(a1f + r0 * ASTR + j)       = lo;
                    *(__half2*)(a1f + (r0 + 8) * ASTR + j) = hi;
                }
    }

    // ---- mono term: single H-table lerp per (row, k), all 512 threads ----
    {
        int r  = tid >> 4;
        int kk = tid & 15;
        const float scale = (float)(NTH - 1) / (2.f * PMAXF);
        float x = __ldg(X + (b0 + r) * INF + kk);
        const float* tk = h_tab + kk * NTH;
        float f = (x + PMAXF) * scale;
        f = fminf(fmaxf(f, 0.f), (float)(NTH - 1) - 1e-3f);
        int i0 = (int)f;
        float fr = f - (float)i0;
        float h0 = tk[i0];
        float h1 = tk[i0 + 1];
        float part = fmaf(fr, h1 - h0, h0) * x * __ldg(wlin + kk);
#pragma unroll
        for (int off = 8; off; off >>= 1)
            part += __shfl_down_sync(0xffffffffu, part, off, 16);
        if ((tid & 15) == 0) mono_s[r] = part;
    }
    __syncthreads();

    // ---- layer 2: fp16 MMA, warp owns 32 cols; B ring, A dbl-buffered ----
    {
        float acc[2][4][4];      // [m][nf 0..3][e]
#pragma unroll
        for (int m = 0; m < 2; m++)
#pragma unroll
            for (int nf = 0; nf < 4; nf++)
#pragma unroll
                for (int e = 0; e < 4; e++) acc[m][nf][e] = 0.f;

        const unsigned a1_u = smem_u32(a1f);
        const uint4* bsm0 = bstage + (2 * warp) * 32 + lane;
        const uint4* bsm1 = bsm0 + 32;

        unsigned a[2][2][4];
#pragma unroll
        for (int m = 0; m < 2; m++) {
            unsigned off = ((m * 16 + arow) * ASTR + acol8) * 2;
            ldsm_x4(a[0][m][0], a[0][m][1], a[0][m][2], a[0][m][3], a1_u + off);
        }
        cp_wait<NST - 2>();                 // stage 0 ready
        uint4 bq0 = bsm0[0];
        uint4 bq1 = bsm1[0];

        for (int kf = 0; kf < 32; kf++) {
            int cur = kf & 1, nxt = cur ^ 1;
            int sl = kf + NST - 1;
            if (sl < 32) {
                cp16(bst0 + (sl & (NST - 1)) * 16384, bgm0 + sl * 1024);
                cp16(bst1 + (sl & (NST - 1)) * 16384, bgm1 + sl * 1024);
            }
            cp_commit();
            if (kf + 1 < 32) {
#pragma unroll
                for (int m = 0; m < 2; m++) {
                    unsigned off = ((m * 16 + arow) * ASTR + (kf + 1) * 16 + acol8) * 2;
                    ldsm_x4(a[nxt][m][0], a[nxt][m][1], a[nxt][m][2], a[nxt][m][3],
                            a1_u + off);
                }
            }
            unsigned bfr[4][2] = {{bq0.x, bq0.y}, {bq0.z, bq0.w},
                                  {bq1.x, bq1.y}, {bq1.z, bq1.w}};
            cp_wait<NST - 2>();
            if (kf + 1 < 32) {
                bq0 = bsm0[((kf + 1) & (NST - 1)) * 1024];
                bq1 = bsm1[((kf + 1) & (NST - 1)) * 1024];
            }
#pragma unroll
            for (int m = 0; m < 2; m++)
#pragma unroll
                for (int nf = 0; nf < 4; nf++)
                    mma_f16(acc[m][nf], a[cur][m], bfr[nf]);
        }

        // epilogue: relu(acc + b2) . w3 -> per-row partials (32-col slice)
#pragma unroll
        for (int m = 0; m < 2; m++) {
            float p0 = 0.f, p1 = 0.f;
#pragma unroll
            for (int nf = 0; nf < 4; nf++) {
                int col = warp * 32 + nf * 8 + (lane & 3) * 2;
                float2 b2v = *(const float2*)(b2 + col);
                float2 w3v = *(const float2*)(w3 + col);
                p0 = fmaf(fmaxf(acc[m][nf][0] + b2v.x, 0.f), w3v.x, p0);
                p0 = fmaf(fmaxf(acc[m][nf][1] + b2v.y, 0.f), w3v.y, p0);
                p1 = fmaf(fmaxf(acc[m][nf][2] + b2v.x, 0.f), w3v.x, p1);
                p1 = fmaf(fmaxf(acc[m][nf][3] + b2v.y, 0.f), w3v.y, p1);
            }
            p0 += __shfl_xor_sync(0xffffffffu, p0, 1);
            p0 += __shfl_xor_sync(0xffffffffu, p0, 2);
            p1 += __shfl_xor_sync(0xffffffffu, p1, 1);
            p1 += __shfl_xor_sync(0xffffffffu, p1, 2);
            if ((lane & 3) == 0) {
                int r0 = m * 16 + (lane >> 2);
                wpart[warp * 32 + r0]     = p0;
                wpart[warp * 32 + r0 + 8] = p1;
            }
        }
    }
    __syncthreads();

    // ---- final: sum 16 warp slices + bias + mono ----
    if (tid < ROWS) {
        float s = 0.f;
#pragma unroll
        for (int w = 0; w < 16; w++) s += wpart[w * 32 + tid];
        out[b0 + tid] = s + __ldg(b3) + mono_s[tid];
    }
}

// ---------------------------------------------------------------------------
extern "C" void kernel_launch(void* const* d_in, const int* in_sizes, int n_in,
                              void* d_out, int out_size)
{
    const float* x    = (const float*)d_in[0];
    const float* mw1  = (const float*)d_in[1];
    const float* mb1  = (const float*)d_in[2];
    const float* mw2  = (const float*)d_in[3];
    const float* mb2  = (const float*)d_in[4];
    const float* mw3  = (const float*)d_in[5];
    const float* mb3  = (const float*)d_in[6];
    const float* wlin = (const float*)d_in[7];
    const float* nw1  = (const float*)d_in[8];
    const float* nb1  = (const float*)d_in[9];
    const float* nw2  = (const float*)d_in[10];
    const float* nb2  = (const float*)d_in[11];
    const float* nw3  = (const float*)d_in[12];
    const float* nb3  = (const float*)d_in[13];
    float* out = (float*)d_out;

    int smem = NST * 1024 * 16
             + (ROWS * ASTR + ROWS * XSTR) * (int)sizeof(__half)
             + (16 * 32 + 32) * (int)sizeof(float);   // ~166 KB
    cudaFuncSetAttribute(fused_kernel, cudaFuncAttributeMaxDynamicSharedMemorySize, smem);

    setup1_kernel<<<344, 256>>>(nw2, nw1, mw1, mb1, mw2, mb2, mw3, mb3);
    hk_kernel<<<KM * NTH / 128, 128>>>();
    fused_kernel<<<B_ / ROWS, 512, smem>>>(x, wlin, nb1, nb2, nw3, nb3, out);
}